// round 7
// baseline (speedup 1.0000x reference)
#include <cuda_runtime.h>
#include <math.h>
#include <stdint.h>

// Problem constants
#define CNU 600000
#define CNI 300000
#define CN  900000     // CNU + CNI
#define CD  64
#define CE  3000000
#define CEI 900000

// ---------------- scratch (device globals; no runtime allocation) ----------
__device__ float g_bufA[(size_t)CN * CD];
__device__ float g_bufB[(size_t)CN * CD];
__device__ float g_h0  [(size_t)CN * CD];
__device__ float g_hcat[(size_t)CNI * 256];
__device__ float g_y   [(size_t)CNI * 256];

// ---------------- helpers ---------------------------------------------------
__device__ __forceinline__ void red_add_v4(float4* addr, float4 v) {
    asm volatile("red.global.add.v4.f32 [%0], {%1,%2,%3,%4};"
                 :: "l"(addr), "f"(v.x), "f"(v.y), "f"(v.z), "f"(v.w)
                 : "memory");
}
__device__ __forceinline__ void cpa16(float* smem, const float* g, bool p) {
    unsigned s = (unsigned)__cvta_generic_to_shared(smem);
    asm volatile("cp.async.cg.shared.global [%0], [%1], 16, %2;\n"
                 :: "r"(s), "l"(g), "r"(p ? 16 : 0));
}
__device__ __forceinline__ void cpa_commit() {
    asm volatile("cp.async.commit_group;\n");
}
__device__ __forceinline__ unsigned f2tf(float f) {
    unsigned u;
    asm("cvt.rna.tf32.f32 %0, %1;" : "=r"(u) : "f"(f));
    return u;
}
__device__ __forceinline__ void mma_tf32(float c[4], const unsigned a[4], const unsigned b[2]) {
    asm volatile("mma.sync.aligned.m16n8k8.row.col.f32.tf32.tf32.f32 "
                 "{%0,%1,%2,%3}, {%4,%5,%6,%7}, {%8,%9}, {%0,%1,%2,%3};"
                 : "+f"(c[0]), "+f"(c[1]), "+f"(c[2]), "+f"(c[3])
                 : "r"(a[0]), "r"(a[1]), "r"(a[2]), "r"(a[3]),
                   "r"(b[0]), "r"(b[1]));
}

// ---------------- init kernel: dst[row*strideQ+offQ+col] = c * src[i] -------
__global__ void init_scaled(const float4* __restrict__ src, float4* __restrict__ dst,
                            float c, int n4, int shift, int mask, int strideQ, int offQ)
{
    int i = blockIdx.x * blockDim.x + threadIdx.x;
    if (i >= n4) return;
    float4 v = src[i];
    v.x *= c; v.y *= c; v.z *= c; v.w *= c;
    int row = i >> shift;
    int col = i & mask;
    dst[(size_t)row * strideQ + offQ + col] = v;
}

// ---------------- column-sliced edge pass -----------------------------------
// LSHIFT = log2(float4 lanes per edge per pass).
template<int LSHIFT>
__global__ void edge_pass(const float4* __restrict__ h,
                          const int* __restrict__ src,
                          const int* __restrict__ dst,
                          const float* __restrict__ w, float wscale,
                          float4* __restrict__ agg,
                          int srcStrideQ, int srcOffQ,
                          int dstStrideQ, int dstOffQ, int ne)
{
    int t = blockIdx.x * blockDim.x + threadIdx.x;
    int e = t >> LSHIFT;
    int lane = t & ((1 << LSHIFT) - 1);
    if (e >= ne) return;
    int s = src[e];
    int d = dst[e];
    float ww = __ldg(&w[e]) * wscale;
    float4 v = h[(size_t)s * srcStrideQ + srcOffQ + lane];
    v.x *= ww; v.y *= ww; v.z *= ww; v.w *= ww;
    red_add_v4(&agg[(size_t)d * dstStrideQ + dstOffQ + lane], v);
}

// ---------------- GEMM1 (TF32 tensor core): C = relu(A[M,256]@B[256,256]+b) -
// BM=128 BN=128 BK=16, 256 threads, warps 4(m)x2(n), warp tile 32x64
__global__ void __launch_bounds__(256)
gemm1_tc(const float* __restrict__ A, const float* __restrict__ B,
         const float* __restrict__ bias, float* __restrict__ C, int M)
{
    __shared__ float As[2][128][20];   // [m][k], pad 4 -> frag lds conflict-free
    __shared__ float Bs[2][16][136];   // [k][n], pad 8 -> <=1-way

    const int tid  = threadIdx.x;
    const int lane = tid & 31;
    const int warp = tid >> 5;
    const int wm   = warp & 3;
    const int wn   = warp >> 2;
    const int g    = lane >> 2;
    const int tg   = lane & 3;
    const int row0 = blockIdx.x * 128;
    const int col0 = blockIdx.y * 128;

    float acc[2][8][4];
    #pragma unroll
    for (int i = 0; i < 2; i++)
        #pragma unroll
        for (int j = 0; j < 8; j++)
            #pragma unroll
            for (int q = 0; q < 4; q++) acc[i][j][q] = 0.f;

    // tile loader
    auto loadTile = [&](int buf, int kt) {
        #pragma unroll
        for (int q = 0; q < 2; q++) {
            int idx = tid + q * 256;
            int r = idx >> 2;
            int kc = (idx & 3) << 2;
            cpa16(&As[buf][r][kc], A + (size_t)(row0 + r) * 256 + kt + kc, (row0 + r) < M);
        }
        #pragma unroll
        for (int q = 0; q < 2; q++) {
            int idx = tid + q * 256;
            int r = idx >> 5;
            int c = (idx & 31) << 2;
            cpa16(&Bs[buf][r][c], B + (size_t)(kt + r) * 256 + col0 + c, true);
        }
        cpa_commit();
    };

    loadTile(0, 0);

    const int NT = 16;
    for (int t = 0; t < NT; t++) {
        int buf = t & 1;
        if (t + 1 < NT) {
            loadTile(buf ^ 1, (t + 1) * 16);
            asm volatile("cp.async.wait_group 1;\n");
        } else {
            asm volatile("cp.async.wait_group 0;\n");
        }
        __syncthreads();

        #pragma unroll
        for (int ks = 0; ks < 2; ks++) {
            const int k0 = ks * 8 + tg;
            unsigned a[2][4], b[8][2];
            #pragma unroll
            for (int mt = 0; mt < 2; mt++) {
                int r = wm * 32 + mt * 16 + g;
                a[mt][0] = f2tf(As[buf][r][k0]);
                a[mt][1] = f2tf(As[buf][r + 8][k0]);
                a[mt][2] = f2tf(As[buf][r][k0 + 4]);
                a[mt][3] = f2tf(As[buf][r + 8][k0 + 4]);
            }
            #pragma unroll
            for (int nt = 0; nt < 8; nt++) {
                int n = wn * 64 + nt * 8 + g;
                b[nt][0] = f2tf(Bs[buf][k0][n]);
                b[nt][1] = f2tf(Bs[buf][k0 + 4][n]);
            }
            #pragma unroll
            for (int mt = 0; mt < 2; mt++)
                #pragma unroll
                for (int nt = 0; nt < 8; nt++)
                    mma_tf32(acc[mt][nt], a[mt], b[nt]);
        }
        __syncthreads();
    }

    // epilogue: bias + relu
    #pragma unroll
    for (int mt = 0; mt < 2; mt++) {
        #pragma unroll
        for (int nt = 0; nt < 8; nt++) {
            int r = row0 + wm * 32 + mt * 16 + g;
            int c = col0 + wn * 64 + nt * 8 + tg * 2;
            float b0 = bias[c], b1 = bias[c + 1];
            if (r < M) {
                float2 v;
                v.x = fmaxf(acc[mt][nt][0] + b0, 0.f);
                v.y = fmaxf(acc[mt][nt][1] + b1, 0.f);
                *(float2*)&C[(size_t)r * 256 + c] = v;
            }
            if (r + 8 < M) {
                float2 v;
                v.x = fmaxf(acc[mt][nt][2] + b0, 0.f);
                v.y = fmaxf(acc[mt][nt][3] + b1, 0.f);
                *(float2*)&C[(size_t)(r + 8) * 256 + c] = v;
            }
        }
    }
}

// ---------------- GEMM2 (TF32): C[M,64] += relu(A[M,256]@B[256,64]+b) -------
// BM=128 BN=64 BK=16, 256 threads, warps 4(m)x2(n), warp tile 32x32
__global__ void __launch_bounds__(256)
gemm2_tc(const float* __restrict__ A, const float* __restrict__ B,
         const float* __restrict__ bias, float* __restrict__ C, int M)
{
    __shared__ float As[2][128][20];
    __shared__ float Bs[2][16][72];

    const int tid  = threadIdx.x;
    const int lane = tid & 31;
    const int warp = tid >> 5;
    const int wm   = warp & 3;
    const int wn   = warp >> 2;
    const int g    = lane >> 2;
    const int tg   = lane & 3;
    const int row0 = blockIdx.x * 128;

    float acc[2][4][4];
    #pragma unroll
    for (int i = 0; i < 2; i++)
        #pragma unroll
        for (int j = 0; j < 4; j++)
            #pragma unroll
            for (int q = 0; q < 4; q++) acc[i][j][q] = 0.f;

    auto loadTile = [&](int buf, int kt) {
        #pragma unroll
        for (int q = 0; q < 2; q++) {
            int idx = tid + q * 256;
            int r = idx >> 2;
            int kc = (idx & 3) << 2;
            cpa16(&As[buf][r][kc], A + (size_t)(row0 + r) * 256 + kt + kc, (row0 + r) < M);
        }
        {
            int r = tid >> 4;
            int c = (tid & 15) << 2;
            cpa16(&Bs[buf][r][c], B + (size_t)(kt + r) * 64 + c, true);
        }
        cpa_commit();
    };

    loadTile(0, 0);

    const int NT = 16;
    for (int t = 0; t < NT; t++) {
        int buf = t & 1;
        if (t + 1 < NT) {
            loadTile(buf ^ 1, (t + 1) * 16);
            asm volatile("cp.async.wait_group 1;\n");
        } else {
            asm volatile("cp.async.wait_group 0;\n");
        }
        __syncthreads();

        #pragma unroll
        for (int ks = 0; ks < 2; ks++) {
            const int k0 = ks * 8 + tg;
            unsigned a[2][4], b[4][2];
            #pragma unroll
            for (int mt = 0; mt < 2; mt++) {
                int r = wm * 32 + mt * 16 + g;
                a[mt][0] = f2tf(As[buf][r][k0]);
                a[mt][1] = f2tf(As[buf][r + 8][k0]);
                a[mt][2] = f2tf(As[buf][r][k0 + 4]);
                a[mt][3] = f2tf(As[buf][r + 8][k0 + 4]);
            }
            #pragma unroll
            for (int nt = 0; nt < 4; nt++) {
                int n = wn * 32 + nt * 8 + g;
                b[nt][0] = f2tf(Bs[buf][k0][n]);
                b[nt][1] = f2tf(Bs[buf][k0 + 4][n]);
            }
            #pragma unroll
            for (int mt = 0; mt < 2; mt++)
                #pragma unroll
                for (int nt = 0; nt < 4; nt++)
                    mma_tf32(acc[mt][nt], a[mt], b[nt]);
        }
        __syncthreads();
    }

    #pragma unroll
    for (int mt = 0; mt < 2; mt++) {
        #pragma unroll
        for (int nt = 0; nt < 4; nt++) {
            int r = row0 + wm * 32 + mt * 16 + g;
            int c = wn * 32 + nt * 8 + tg * 2;
            float b0 = bias[c], b1 = bias[c + 1];
            if (r < M) {
                float2* cp = (float2*)&C[(size_t)r * 64 + c];
                float2 o = *cp;
                o.x += fmaxf(acc[mt][nt][0] + b0, 0.f);
                o.y += fmaxf(acc[mt][nt][1] + b1, 0.f);
                *cp = o;
            }
            if (r + 8 < M) {
                float2* cp = (float2*)&C[(size_t)(r + 8) * 64 + c];
                float2 o = *cp;
                o.x += fmaxf(acc[mt][nt][2] + b0, 0.f);
                o.y += fmaxf(acc[mt][nt][3] + b1, 0.f);
                *cp = o;
            }
        }
    }
}

// ---------------- launch ----------------------------------------------------
extern "C" void kernel_launch(void* const* d_in, const int* in_sizes, int n_in,
                              void* d_out, int out_size)
{
    (void)in_sizes; (void)n_in; (void)out_size;
    const float* user_emb = (const float*)d_in[0];
    const float* item_emb = (const float*)d_in[1];
    const float* feat0    = (const float*)d_in[2];
    const float* feat1    = (const float*)d_in[3];
    const float* gw       = (const float*)d_in[4];
    const float* ig0w     = (const float*)d_in[5];
    const float* ig1w     = (const float*)d_in[6];
    const float* W1       = (const float*)d_in[7];
    const float* b1       = (const float*)d_in[8];
    const float* W2       = (const float*)d_in[9];
    const float* b2       = (const float*)d_in[10];
    const int* gsrc  = (const int*)d_in[11];
    const int* gdst  = (const int*)d_in[12];
    const int* i0src = (const int*)d_in[13];
    const int* i0dst = (const int*)d_in[14];
    const int* i1src = (const int*)d_in[15];
    const int* i1dst = (const int*)d_in[16];
    float* out = (float*)d_out;

    float *bufA, *bufB, *h0_, *hcat_, *y_;
    cudaGetSymbolAddress((void**)&bufA, g_bufA);
    cudaGetSymbolAddress((void**)&bufB, g_bufB);
    cudaGetSymbolAddress((void**)&h0_,  g_h0);
    cudaGetSymbolAddress((void**)&hcat_, g_hcat);
    cudaGetSymbolAddress((void**)&y_,   g_y);

    const float ALPHA = 0.1f, BETA = 0.9f;
    double g2 = 0.9 * 0.9 + 0.1 * (1.0 + 0.9);
    double g4 = 0.9 * 0.9 * 0.9 * 0.9 + 0.1 * (1.0 + 0.9 + 0.81 + 0.729);
    const float ab  = ALPHA / BETA;
    const float ag2 = (float)(0.1 / g2);
    const float ag4 = (float)(0.1 / g4);
    const float wb  = BETA;
    const float wf2 = (float)(0.9 * 0.9 / g2);
    const float wf4 = (float)(0.9 * 0.9 / g4);

    cudaStream_t s = 0;
    const int TPB = 256;
    const int n4_N = CN * CD / 4;
    const int n4_I = CNI * 128 / 4;
    const int iB_N = (n4_N + TPB - 1) / TPB;
    const int iB_I = (n4_I + TPB - 1) / TPB;
    // item graphs: 4 col passes x 8 float4 lanes (32 floats) per edge
    const int eBI = (CEI * 8 + TPB - 1) / TPB;
    // bipartite: 4 col passes x 4 float4 lanes (16 floats) per edge
    const int eBG = (CE * 4 + TPB - 1) / TPB;

    // ===== item graph 0: 4 hops -> hcat[:, 0:128] =====
    init_scaled<<<iB_I, TPB, 0, s>>>((const float4*)feat0, (float4*)bufB, ab, n4_I, 0, 0, 1, 0);
    for (int p = 0; p < 4; p++)
        edge_pass<3><<<eBI, TPB, 0, s>>>((const float4*)feat0, i0src, i0dst, ig0w, 1.0f,
                                         (float4*)bufB, 32, p * 8, 32, p * 8, CEI);
    init_scaled<<<iB_I, TPB, 0, s>>>((const float4*)feat0, (float4*)bufA, ab, n4_I, 0, 0, 1, 0);
    for (int p = 0; p < 4; p++)
        edge_pass<3><<<eBI, TPB, 0, s>>>((const float4*)bufB, i0src, i0dst, ig0w, wb,
                                         (float4*)bufA, 32, p * 8, 32, p * 8, CEI);
    init_scaled<<<iB_I, TPB, 0, s>>>((const float4*)feat0, (float4*)bufB, ab, n4_I, 0, 0, 1, 0);
    for (int p = 0; p < 4; p++)
        edge_pass<3><<<eBI, TPB, 0, s>>>((const float4*)bufA, i0src, i0dst, ig0w, wb,
                                         (float4*)bufB, 32, p * 8, 32, p * 8, CEI);
    init_scaled<<<iB_I, TPB, 0, s>>>((const float4*)feat0, (float4*)hcat_, ag4, n4_I, 5, 31, 64, 0);
    for (int p = 0; p < 4; p++)
        edge_pass<3><<<eBI, TPB, 0, s>>>((const float4*)bufB, i0src, i0dst, ig0w, wf4,
                                         (float4*)hcat_, 32, p * 8, 64, p * 8, CEI);

    // ===== item graph 1: 2 hops -> hcat[:, 128:256] =====
    init_scaled<<<iB_I, TPB, 0, s>>>((const float4*)feat1, (float4*)bufB, ab, n4_I, 0, 0, 1, 0);
    for (int p = 0; p < 4; p++)
        edge_pass<3><<<eBI, TPB, 0, s>>>((const float4*)feat1, i1src, i1dst, ig1w, 1.0f,
                                         (float4*)bufB, 32, p * 8, 32, p * 8, CEI);
    init_scaled<<<iB_I, TPB, 0, s>>>((const float4*)feat1, (float4*)hcat_, ag2, n4_I, 5, 31, 64, 32);
    for (int p = 0; p < 4; p++)
        edge_pass<3><<<eBI, TPB, 0, s>>>((const float4*)bufB, i1src, i1dst, ig1w, wf2,
                                         (float4*)hcat_, 32, p * 8, 64, 32 + p * 8, CEI);

    // ===== GEMM1: y = relu(hcat @ W1 + b1) =====
    {
        dim3 grid((CNI + 127) / 128, 2);
        gemm1_tc<<<grid, 256, 0, s>>>(hcat_, W1, b1, y_, CNI);
    }

    // ===== bipartite: 2 hops -> out =====
    cudaMemcpyAsync(h0_, user_emb, (size_t)CNU * CD * sizeof(float),
                    cudaMemcpyDeviceToDevice, s);
    cudaMemcpyAsync(h0_ + (size_t)CNU * CD, item_emb, (size_t)CNI * CD * sizeof(float),
                    cudaMemcpyDeviceToDevice, s);
    init_scaled<<<iB_N, TPB, 0, s>>>((const float4*)h0_, (float4*)bufA, ab, n4_N, 0, 0, 1, 0);
    for (int p = 0; p < 4; p++)
        edge_pass<2><<<eBG, TPB, 0, s>>>((const float4*)h0_, gsrc, gdst, gw, 1.0f,
                                         (float4*)bufA, 16, p * 4, 16, p * 4, CE);
    init_scaled<<<iB_N, TPB, 0, s>>>((const float4*)h0_, (float4*)out, ag2, n4_N, 0, 0, 1, 0);
    for (int p = 0; p < 4; p++)
        edge_pass<2><<<eBG, TPB, 0, s>>>((const float4*)bufA, gsrc, gdst, gw, wf2,
                                         (float4*)out, 16, p * 4, 16, p * 4, CE);

    // ===== GEMM2: out[NU:] += relu(y @ W2 + b2) =====
    gemm2_tc<<<(CNI + 127) / 128, 256, 0, s>>>(y_, W2, b2,
                                               out + (size_t)CNU * CD, CNI);
}

// round 8
// speedup vs baseline: 1.0275x; 1.0275x over previous
#include <cuda_runtime.h>
#include <math.h>
#include <stdint.h>

// Problem constants
#define CNU 600000
#define CNI 300000
#define CN  900000     // CNU + CNI
#define CD  64
#define CE  3000000
#define CEI 900000

// ---------------- scratch (device globals; no runtime allocation) ----------
__device__ float g_bufA[(size_t)CN * CD];
__device__ float g_bufB[(size_t)CN * CD];
__device__ float g_h0  [(size_t)CN * CD];
__device__ float g_hcat[(size_t)CNI * 256];
__device__ float g_y   [(size_t)CNI * 256];

// ---------------- helpers ---------------------------------------------------
__device__ __forceinline__ void red_add_v4(float4* addr, float4 v) {
    asm volatile("red.global.add.v4.f32 [%0], {%1,%2,%3,%4};"
                 :: "l"(addr), "f"(v.x), "f"(v.y), "f"(v.z), "f"(v.w)
                 : "memory");
}
__device__ __forceinline__ void cpa16(float* smem, const float* g, bool p) {
    unsigned s = (unsigned)__cvta_generic_to_shared(smem);
    asm volatile("cp.async.cg.shared.global [%0], [%1], 16, %2;\n"
                 :: "r"(s), "l"(g), "r"(p ? 16 : 0));
}
__device__ __forceinline__ void cpa_commit() {
    asm volatile("cp.async.commit_group;\n");
}
__device__ __forceinline__ unsigned f2tf(float f) {
    unsigned u;
    asm("cvt.rna.tf32.f32 %0, %1;" : "=r"(u) : "f"(f));
    return u;
}
__device__ __forceinline__ void mma_tf32(float c[4], const unsigned a[4], const unsigned b[2]) {
    asm volatile("mma.sync.aligned.m16n8k8.row.col.f32.tf32.tf32.f32 "
                 "{%0,%1,%2,%3}, {%4,%5,%6,%7}, {%8,%9}, {%0,%1,%2,%3};"
                 : "+f"(c[0]), "+f"(c[1]), "+f"(c[2]), "+f"(c[3])
                 : "r"(a[0]), "r"(a[1]), "r"(a[2]), "r"(a[3]),
                   "r"(b[0]), "r"(b[1]));
}

// ---------------- init kernel: dst[row*strideQ+offQ+col] = c * src[i] -------
__global__ void init_scaled(const float4* __restrict__ src, float4* __restrict__ dst,
                            float c, int n4, int shift, int mask, int strideQ, int offQ)
{
    int i = blockIdx.x * blockDim.x + threadIdx.x;
    if (i >= n4) return;
    float4 v = src[i];
    v.x *= c; v.y *= c; v.z *= c; v.w *= c;
    int row = i >> shift;
    int col = i & mask;
    dst[(size_t)row * strideQ + offQ + col] = v;
}

// ---------------- column-sliced edge pass -----------------------------------
// LSHIFT = log2(float4 lanes per edge per pass).
template<int LSHIFT>
__global__ void edge_pass(const float4* __restrict__ h,
                          const int* __restrict__ src,
                          const int* __restrict__ dst,
                          const float* __restrict__ w, float wscale,
                          float4* __restrict__ agg,
                          int srcStrideQ, int srcOffQ,
                          int dstStrideQ, int dstOffQ, int ne)
{
    int t = blockIdx.x * blockDim.x + threadIdx.x;
    int e = t >> LSHIFT;
    int lane = t & ((1 << LSHIFT) - 1);
    if (e >= ne) return;
    int s = src[e];
    int d = dst[e];
    float ww = __ldg(&w[e]) * wscale;
    float4 v = h[(size_t)s * srcStrideQ + srcOffQ + lane];
    v.x *= ww; v.y *= ww; v.z *= ww; v.w *= ww;
    red_add_v4(&agg[(size_t)d * dstStrideQ + dstOffQ + lane], v);
}

// ---------------- GEMM1 (TF32 tensor core): C = relu(A[M,256]@B[256,256]+b) -
// BM=128 BN=128 BK=16, 256 threads, warps 4(m)x2(n), warp tile 32x64
__global__ void __launch_bounds__(256)
gemm1_tc(const float* __restrict__ A, const float* __restrict__ B,
         const float* __restrict__ bias, float* __restrict__ C, int M)
{
    __shared__ float As[2][128][20];   // [m][k], pad 4 -> frag lds conflict-free
    __shared__ float Bs[2][16][136];   // [k][n], pad 8 -> <=1-way

    const int tid  = threadIdx.x;
    const int lane = tid & 31;
    const int warp = tid >> 5;
    const int wm   = warp & 3;
    const int wn   = warp >> 2;
    const int g    = lane >> 2;
    const int tg   = lane & 3;
    const int row0 = blockIdx.x * 128;
    const int col0 = blockIdx.y * 128;

    float acc[2][8][4];
    #pragma unroll
    for (int i = 0; i < 2; i++)
        #pragma unroll
        for (int j = 0; j < 8; j++)
            #pragma unroll
            for (int q = 0; q < 4; q++) acc[i][j][q] = 0.f;

    // tile loader
    auto loadTile = [&](int buf, int kt) {
        #pragma unroll
        for (int q = 0; q < 2; q++) {
            int idx = tid + q * 256;
            int r = idx >> 2;
            int kc = (idx & 3) << 2;
            cpa16(&As[buf][r][kc], A + (size_t)(row0 + r) * 256 + kt + kc, (row0 + r) < M);
        }
        #pragma unroll
        for (int q = 0; q < 2; q++) {
            int idx = tid + q * 256;
            int r = idx >> 5;
            int c = (idx & 31) << 2;
            cpa16(&Bs[buf][r][c], B + (size_t)(kt + r) * 256 + col0 + c, true);
        }
        cpa_commit();
    };

    loadTile(0, 0);

    const int NT = 16;
    for (int t = 0; t < NT; t++) {
        int buf = t & 1;
        if (t + 1 < NT) {
            loadTile(buf ^ 1, (t + 1) * 16);
            asm volatile("cp.async.wait_group 1;\n");
        } else {
            asm volatile("cp.async.wait_group 0;\n");
        }
        __syncthreads();

        #pragma unroll
        for (int ks = 0; ks < 2; ks++) {
            const int k0 = ks * 8 + tg;
            unsigned a[2][4], b[8][2];
            #pragma unroll
            for (int mt = 0; mt < 2; mt++) {
                int r = wm * 32 + mt * 16 + g;
                a[mt][0] = f2tf(As[buf][r][k0]);
                a[mt][1] = f2tf(As[buf][r + 8][k0]);
                a[mt][2] = f2tf(As[buf][r][k0 + 4]);
                a[mt][3] = f2tf(As[buf][r + 8][k0 + 4]);
            }
            #pragma unroll
            for (int nt = 0; nt < 8; nt++) {
                int n = wn * 64 + nt * 8 + g;
                b[nt][0] = f2tf(Bs[buf][k0][n]);
                b[nt][1] = f2tf(Bs[buf][k0 + 4][n]);
            }
            #pragma unroll
            for (int mt = 0; mt < 2; mt++)
                #pragma unroll
                for (int nt = 0; nt < 8; nt++)
                    mma_tf32(acc[mt][nt], a[mt], b[nt]);
        }
        __syncthreads();
    }

    // epilogue: bias + relu
    #pragma unroll
    for (int mt = 0; mt < 2; mt++) {
        #pragma unroll
        for (int nt = 0; nt < 8; nt++) {
            int r = row0 + wm * 32 + mt * 16 + g;
            int c = col0 + wn * 64 + nt * 8 + tg * 2;
            float b0 = bias[c], b1 = bias[c + 1];
            if (r < M) {
                float2 v;
                v.x = fmaxf(acc[mt][nt][0] + b0, 0.f);
                v.y = fmaxf(acc[mt][nt][1] + b1, 0.f);
                *(float2*)&C[(size_t)r * 256 + c] = v;
            }
            if (r + 8 < M) {
                float2 v;
                v.x = fmaxf(acc[mt][nt][2] + b0, 0.f);
                v.y = fmaxf(acc[mt][nt][3] + b1, 0.f);
                *(float2*)&C[(size_t)(r + 8) * 256 + c] = v;
            }
        }
    }
}

// ---------------- GEMM2 (TF32): C[M,64] += relu(A[M,256]@B[256,64]+b) -------
// BM=128 BN=64 BK=16, 256 threads, warps 4(m)x2(n), warp tile 32x32
__global__ void __launch_bounds__(256)
gemm2_tc(const float* __restrict__ A, const float* __restrict__ B,
         const float* __restrict__ bias, float* __restrict__ C, int M)
{
    __shared__ float As[2][128][20];
    __shared__ float Bs[2][16][72];

    const int tid  = threadIdx.x;
    const int lane = tid & 31;
    const int warp = tid >> 5;
    const int wm   = warp & 3;
    const int wn   = warp >> 2;
    const int g    = lane >> 2;
    const int tg   = lane & 3;
    const int row0 = blockIdx.x * 128;

    float acc[2][4][4];
    #pragma unroll
    for (int i = 0; i < 2; i++)
        #pragma unroll
        for (int j = 0; j < 4; j++)
            #pragma unroll
            for (int q = 0; q < 4; q++) acc[i][j][q] = 0.f;

    auto loadTile = [&](int buf, int kt) {
        #pragma unroll
        for (int q = 0; q < 2; q++) {
            int idx = tid + q * 256;
            int r = idx >> 2;
            int kc = (idx & 3) << 2;
            cpa16(&As[buf][r][kc], A + (size_t)(row0 + r) * 256 + kt + kc, (row0 + r) < M);
        }
        {
            int r = tid >> 4;
            int c = (tid & 15) << 2;
            cpa16(&Bs[buf][r][c], B + (size_t)(kt + r) * 64 + c, true);
        }
        cpa_commit();
    };

    loadTile(0, 0);

    const int NT = 16;
    for (int t = 0; t < NT; t++) {
        int buf = t & 1;
        if (t + 1 < NT) {
            loadTile(buf ^ 1, (t + 1) * 16);
            asm volatile("cp.async.wait_group 1;\n");
        } else {
            asm volatile("cp.async.wait_group 0;\n");
        }
        __syncthreads();

        #pragma unroll
        for (int ks = 0; ks < 2; ks++) {
            const int k0 = ks * 8 + tg;
            unsigned a[2][4], b[4][2];
            #pragma unroll
            for (int mt = 0; mt < 2; mt++) {
                int r = wm * 32 + mt * 16 + g;
                a[mt][0] = f2tf(As[buf][r][k0]);
                a[mt][1] = f2tf(As[buf][r + 8][k0]);
                a[mt][2] = f2tf(As[buf][r][k0 + 4]);
                a[mt][3] = f2tf(As[buf][r + 8][k0 + 4]);
            }
            #pragma unroll
            for (int nt = 0; nt < 4; nt++) {
                int n = wn * 32 + nt * 8 + g;
                b[nt][0] = f2tf(Bs[buf][k0][n]);
                b[nt][1] = f2tf(Bs[buf][k0 + 4][n]);
            }
            #pragma unroll
            for (int mt = 0; mt < 2; mt++)
                #pragma unroll
                for (int nt = 0; nt < 4; nt++)
                    mma_tf32(acc[mt][nt], a[mt], b[nt]);
        }
        __syncthreads();
    }

    #pragma unroll
    for (int mt = 0; mt < 2; mt++) {
        #pragma unroll
        for (int nt = 0; nt < 4; nt++) {
            int r = row0 + wm * 32 + mt * 16 + g;
            int c = wn * 32 + nt * 8 + tg * 2;
            float b0 = bias[c], b1 = bias[c + 1];
            if (r < M) {
                float2* cp = (float2*)&C[(size_t)r * 64 + c];
                float2 o = *cp;
                o.x += fmaxf(acc[mt][nt][0] + b0, 0.f);
                o.y += fmaxf(acc[mt][nt][1] + b1, 0.f);
                *cp = o;
            }
            if (r + 8 < M) {
                float2* cp = (float2*)&C[(size_t)(r + 8) * 64 + c];
                float2 o = *cp;
                o.x += fmaxf(acc[mt][nt][2] + b0, 0.f);
                o.y += fmaxf(acc[mt][nt][3] + b1, 0.f);
                *cp = o;
            }
        }
    }
}

// ---------------- launch ----------------------------------------------------
extern "C" void kernel_launch(void* const* d_in, const int* in_sizes, int n_in,
                              void* d_out, int out_size)
{
    (void)in_sizes; (void)n_in; (void)out_size;
    const float* user_emb = (const float*)d_in[0];
    const float* item_emb = (const float*)d_in[1];
    const float* feat0    = (const float*)d_in[2];
    const float* feat1    = (const float*)d_in[3];
    const float* gw       = (const float*)d_in[4];
    const float* ig0w     = (const float*)d_in[5];
    const float* ig1w     = (const float*)d_in[6];
    const float* W1       = (const float*)d_in[7];
    const float* b1       = (const float*)d_in[8];
    const float* W2       = (const float*)d_in[9];
    const float* b2       = (const float*)d_in[10];
    const int* gsrc  = (const int*)d_in[11];
    const int* gdst  = (const int*)d_in[12];
    const int* i0src = (const int*)d_in[13];
    const int* i0dst = (const int*)d_in[14];
    const int* i1src = (const int*)d_in[15];
    const int* i1dst = (const int*)d_in[16];
    float* out = (float*)d_out;

    float *bufA, *bufB, *h0_, *hcat_, *y_;
    cudaGetSymbolAddress((void**)&bufA, g_bufA);
    cudaGetSymbolAddress((void**)&bufB, g_bufB);
    cudaGetSymbolAddress((void**)&h0_,  g_h0);
    cudaGetSymbolAddress((void**)&hcat_, g_hcat);
    cudaGetSymbolAddress((void**)&y_,   g_y);

    const float ALPHA = 0.1f, BETA = 0.9f;
    double g2 = 0.9 * 0.9 + 0.1 * (1.0 + 0.9);
    double g4 = 0.9 * 0.9 * 0.9 * 0.9 + 0.1 * (1.0 + 0.9 + 0.81 + 0.729);
    const float ab  = ALPHA / BETA;
    const float ag2 = (float)(0.1 / g2);
    const float ag4 = (float)(0.1 / g4);
    const float wb  = BETA;
    const float wf2 = (float)(0.9 * 0.9 / g2);
    const float wf4 = (float)(0.9 * 0.9 / g4);

    cudaStream_t s = 0;
    const int TPB = 256;
    const int n4_N = CN * CD / 4;
    const int n4_I = CNI * 128 / 4;
    const int iB_N = (n4_N + TPB - 1) / TPB;
    const int iB_I = (n4_I + TPB - 1) / TPB;
    // item graphs: 4 col passes x 8 float4 lanes (32 floats) per edge
    const int eBI = (CEI * 8 + TPB - 1) / TPB;
    // bipartite: 4 col passes x 4 float4 lanes (16 floats) per edge
    const int eBG = (CE * 4 + TPB - 1) / TPB;

    // ===== item graph 0: 4 hops -> hcat[:, 0:128] =====
    init_scaled<<<iB_I, TPB, 0, s>>>((const float4*)feat0, (float4*)bufB, ab, n4_I, 0, 0, 1, 0);
    for (int p = 0; p < 4; p++)
        edge_pass<3><<<eBI, TPB, 0, s>>>((const float4*)feat0, i0src, i0dst, ig0w, 1.0f,
                                         (float4*)bufB, 32, p * 8, 32, p * 8, CEI);
    init_scaled<<<iB_I, TPB, 0, s>>>((const float4*)feat0, (float4*)bufA, ab, n4_I, 0, 0, 1, 0);
    for (int p = 0; p < 4; p++)
        edge_pass<3><<<eBI, TPB, 0, s>>>((const float4*)bufB, i0src, i0dst, ig0w, wb,
                                         (float4*)bufA, 32, p * 8, 32, p * 8, CEI);
    init_scaled<<<iB_I, TPB, 0, s>>>((const float4*)feat0, (float4*)bufB, ab, n4_I, 0, 0, 1, 0);
    for (int p = 0; p < 4; p++)
        edge_pass<3><<<eBI, TPB, 0, s>>>((const float4*)bufA, i0src, i0dst, ig0w, wb,
                                         (float4*)bufB, 32, p * 8, 32, p * 8, CEI);
    init_scaled<<<iB_I, TPB, 0, s>>>((const float4*)feat0, (float4*)hcat_, ag4, n4_I, 5, 31, 64, 0);
    for (int p = 0; p < 4; p++)
        edge_pass<3><<<eBI, TPB, 0, s>>>((const float4*)bufB, i0src, i0dst, ig0w, wf4,
                                         (float4*)hcat_, 32, p * 8, 64, p * 8, CEI);

    // ===== item graph 1: 2 hops -> hcat[:, 128:256] =====
    init_scaled<<<iB_I, TPB, 0, s>>>((const float4*)feat1, (float4*)bufB, ab, n4_I, 0, 0, 1, 0);
    for (int p = 0; p < 4; p++)
        edge_pass<3><<<eBI, TPB, 0, s>>>((const float4*)feat1, i1src, i1dst, ig1w, 1.0f,
                                         (float4*)bufB, 32, p * 8, 32, p * 8, CEI);
    init_scaled<<<iB_I, TPB, 0, s>>>((const float4*)feat1, (float4*)hcat_, ag2, n4_I, 5, 31, 64, 32);
    for (int p = 0; p < 4; p++)
        edge_pass<3><<<eBI, TPB, 0, s>>>((const float4*)bufB, i1src, i1dst, ig1w, wf2,
                                         (float4*)hcat_, 32, p * 8, 64, 32 + p * 8, CEI);

    // ===== GEMM1: y = relu(hcat @ W1 + b1) =====
    {
        dim3 grid((CNI + 127) / 128, 2);
        gemm1_tc<<<grid, 256, 0, s>>>(hcat_, W1, b1, y_, CNI);
    }

    // ===== bipartite: 2 hops -> out =====
    cudaMemcpyAsync(h0_, user_emb, (size_t)CNU * CD * sizeof(float),
                    cudaMemcpyDeviceToDevice, s);
    cudaMemcpyAsync(h0_ + (size_t)CNU * CD, item_emb, (size_t)CNI * CD * sizeof(float),
                    cudaMemcpyDeviceToDevice, s);
    init_scaled<<<iB_N, TPB, 0, s>>>((const float4*)h0_, (float4*)bufA, ab, n4_N, 0, 0, 1, 0);
    for (int p = 0; p < 4; p++)
        edge_pass<2><<<eBG, TPB, 0, s>>>((const float4*)h0_, gsrc, gdst, gw, 1.0f,
                                         (float4*)bufA, 16, p * 4, 16, p * 4, CE);
    init_scaled<<<iB_N, TPB, 0, s>>>((const float4*)h0_, (float4*)out, ag2, n4_N, 0, 0, 1, 0);
    for (int p = 0; p < 4; p++)
        edge_pass<2><<<eBG, TPB, 0, s>>>((const float4*)bufA, gsrc, gdst, gw, wf2,
                                         (float4*)out, 16, p * 4, 16, p * 4, CE);

    // ===== GEMM2: out[NU:] += relu(y @ W2 + b2) =====
    gemm2_tc<<<(CNI + 127) / 128, 256, 0, s>>>(y_, W2, b2,
                                               out + (size_t)CNU * CD, CNI);
}